// round 1
// baseline (speedup 1.0000x reference)
#include <cuda_runtime.h>
#include <math.h>

#define SEQ   256
#define NB    32
#define REC   16
#define EMB   32
#define VOCAB 32000
#define ROWS  (SEQ*NB)        /* 8192 */

/* pass A (sum-exp) config */
#define PA_THREADS  128
#define PA_CHUNK    500       /* 64 * 500 = 32000 */
#define PA_NCHUNK   64
#define PA_ROWTILES 64        /* 64 * 128 = 8192 rows */

/* pass B (write) config */
#define PB_THREADS 256
#define PB_ROWS    32
#define PB_COLS    (PB_THREADS*2)   /* 512 cols per block */
#define PB_NCHUNK  63               /* ceil(32000/512) */

__device__ float g_ih[ROWS*REC];
__device__ float g_hidden[ROWS*REC];
__device__ float g_part[ROWS*PA_NCHUNK];
__device__ float g_lse[ROWS];

/* ---------------- kernel 1: i_h = emb[idx] @ U^T + b1 ---------------- */
__global__ void k_ih(const int* __restrict__ inp, const float* __restrict__ emb,
                     const float* __restrict__ U, const float* __restrict__ b1)
{
    int gid = blockIdx.x*blockDim.x + threadIdx.x;
    if (gid >= ROWS*REC) return;
    int row = gid >> 4;
    int r   = gid & 15;
    int idx = inp[row];
    const float4* e4 = (const float4*)(emb + (size_t)idx*EMB);
    const float4* u4 = (const float4*)(U + r*EMB);
    float acc = b1[r];
    #pragma unroll
    for (int q = 0; q < 8; q++) {
        float4 e = e4[q], u = u4[q];
        acc += e.x*u.x + e.y*u.y + e.z*u.z + e.w*u.w;
    }
    g_ih[gid] = acc;
}

/* ---------------- kernel 2: sequential recurrence (1 warp / batch) ----
   hidden[s] stores h BEFORE the update (matches reference scan).        */
__global__ void k_rnn(const float* __restrict__ W, const float* __restrict__ b2,
                      const float* __restrict__ h0)
{
    int b = blockIdx.x;
    int r = threadIdx.x;
    __shared__ float hs[REC];
    float wrow[REC];
    float bias = 0.f;
    if (r < REC) {
        hs[r] = h0[r];
        #pragma unroll
        for (int k = 0; k < REC; k++) wrow[k] = W[r*REC + k];
        bias = b2[r];
    }
    __syncwarp();
    for (int s = 0; s < SEQ; s++) {
        float hn = 0.f;
        if (r < REC) {
            int row = s*NB + b;
            g_hidden[row*REC + r] = hs[r];          /* pre-update h */
            float acc = g_ih[row*REC + r] + bias;
            #pragma unroll
            for (int k = 0; k < REC; k++) acc += wrow[k]*hs[k];
            hn = tanhf(acc);
        }
        __syncwarp();
        if (r < REC) hs[r] = hn;
        __syncwarp();
    }
}

/* ---------------- kernel 3: per-row sum of exp(logit) over a vocab chunk.
   thread <-> row; V chunk transposed into shared so 4 adjacent columns
   load as one broadcast LDS.128 per k.                                   */
__global__ void k_sumexp(const float* __restrict__ V)
{
    __shared__ __align__(16) float Vs[REC*PA_CHUNK];   /* 31.25 KB */
    int cBase = blockIdx.x * PA_CHUNK;
    int row   = blockIdx.y * PA_THREADS + threadIdx.x;

    for (int i = threadIdx.x; i < PA_CHUNK*4; i += PA_THREADS) {
        int c = i >> 2, kq = i & 3;
        float4 v = ((const float4*)(V + (size_t)(cBase + c)*REC))[kq];
        Vs[(kq*4+0)*PA_CHUNK + c] = v.x;
        Vs[(kq*4+1)*PA_CHUNK + c] = v.y;
        Vs[(kq*4+2)*PA_CHUNK + c] = v.z;
        Vs[(kq*4+3)*PA_CHUNK + c] = v.w;
    }
    __syncthreads();

    float h[REC];
    {
        const float4* h4 = (const float4*)(g_hidden + (size_t)row*REC);
        #pragma unroll
        for (int q = 0; q < 4; q++) {
            float4 t = h4[q];
            h[q*4+0]=t.x; h[q*4+1]=t.y; h[q*4+2]=t.z; h[q*4+3]=t.w;
        }
    }

    float acc = 0.f;
    for (int c = 0; c < PA_CHUNK; c += 4) {
        float d0=0.f, d1=0.f, d2=0.f, d3=0.f;
        #pragma unroll
        for (int k = 0; k < REC; k++) {
            float4 v = *(const float4*)&Vs[k*PA_CHUNK + c];
            d0 += h[k]*v.x; d1 += h[k]*v.y; d2 += h[k]*v.z; d3 += h[k]*v.w;
        }
        acc += __expf(d0) + __expf(d1) + __expf(d2) + __expf(d3);
    }
    g_part[(size_t)row*PA_NCHUNK + blockIdx.x] = acc;
}

/* ---------------- kernel 4: lse[row] = log(sum of partials) ---------- */
__global__ void k_lse()
{
    int row = blockIdx.x*blockDim.x + threadIdx.x;
    if (row >= ROWS) return;
    float s = 0.f;
    #pragma unroll
    for (int i = 0; i < PA_NCHUNK; i++) s += g_part[(size_t)row*PA_NCHUNK + i];
    g_lse[row] = logf(s);
}

/* ---------------- kernel 5: out = logit - lse (recompute GEMM) --------
   thread <-> 2 adjacent cols (V rows in regs, coalesced LDG.128 / STG.64),
   loop over 32 rows with h broadcast from shared.                        */
__global__ void k_write(const float* __restrict__ V, float* __restrict__ out)
{
    __shared__ __align__(16) float hs[PB_ROWS*REC];   /* 2 KB */
    __shared__ float ls[PB_ROWS];
    int rowBase = blockIdx.y * PB_ROWS;
    int cBase   = blockIdx.x * PB_COLS;
    int c0      = cBase + threadIdx.x*2;

    if (threadIdx.x < PB_ROWS*REC/4)
        ((float4*)hs)[threadIdx.x] =
            ((const float4*)(g_hidden + (size_t)rowBase*REC))[threadIdx.x];
    if (threadIdx.x < PB_ROWS)
        ls[threadIdx.x] = g_lse[rowBase + threadIdx.x];
    __syncthreads();

    if (c0 >= VOCAB) return;

    float v0[REC], v1[REC];
    {
        const float4* p0 = (const float4*)(V + (size_t)c0*REC);
        const float4* p1 = (const float4*)(V + (size_t)(c0+1)*REC);
        #pragma unroll
        for (int q = 0; q < 4; q++) {
            float4 a = p0[q];
            v0[q*4+0]=a.x; v0[q*4+1]=a.y; v0[q*4+2]=a.z; v0[q*4+3]=a.w;
            float4 b = p1[q];
            v1[q*4+0]=b.x; v1[q*4+1]=b.y; v1[q*4+2]=b.z; v1[q*4+3]=b.w;
        }
    }

    for (int rr = 0; rr < PB_ROWS; rr++) {
        const float4* hh = (const float4*)(hs + rr*REC);
        float4 a = hh[0], b = hh[1], c = hh[2], d = hh[3];
        float h[REC] = {a.x,a.y,a.z,a.w, b.x,b.y,b.z,b.w,
                        c.x,c.y,c.z,c.w, d.x,d.y,d.z,d.w};
        float acc0 = 0.f, acc1 = 0.f;
        #pragma unroll
        for (int k = 0; k < REC; k++) {
            acc0 += h[k]*v0[k];
            acc1 += h[k]*v1[k];
        }
        float l = ls[rr];
        float2 o; o.x = acc0 - l; o.y = acc1 - l;
        *(float2*)(out + (size_t)(rowBase+rr)*VOCAB + c0) = o;
    }
}

extern "C" void kernel_launch(void* const* d_in, const int* in_sizes, int n_in,
                              void* d_out, int out_size)
{
    const int*   inp = (const int*)d_in[0];
    const float* emb = (const float*)d_in[1];
    const float* U   = (const float*)d_in[2];
    const float* W   = (const float*)d_in[3];
    const float* V   = (const float*)d_in[4];
    const float* b1  = (const float*)d_in[5];
    const float* b2  = (const float*)d_in[6];
    const float* h0  = (const float*)d_in[7];
    float* out = (float*)d_out;

    k_ih<<<(ROWS*REC + 255)/256, 256>>>(inp, emb, U, b1);
    k_rnn<<<NB, 32>>>(W, b2, h0);
    k_sumexp<<<dim3(PA_NCHUNK, PA_ROWTILES), PA_THREADS>>>(V);
    k_lse<<<(ROWS + 255)/256, 256>>>();
    k_write<<<dim3(PB_NCHUNK, ROWS/PB_ROWS), PB_THREADS>>>(V, out);
}